// round 1
// baseline (speedup 1.0000x reference)
#include <cuda_runtime.h>
#include <stdint.h>

#define NB   16
#define KMAX 50
#define NG   76
#define NA   3
#define NCLS 80
#define NCH  85           // 5 + NCLS
#define CELLS (NA*NG*NG)  // 17328
#define BLK  256
#define NBLK ((CELLS + BLK - 1)/BLK)   // 68

// Scratch: per-(b,k) prep record, 12 words:
// [0..3] gt corners x1,y1,x2,y2  [4] gt area
// [5..8] targets t0..t3          [9] w2
// [10] cell index (int, -1 invalid)  [11] class (int)
__device__ float  g_prep[NB][KMAX][12];
__device__ double g_partial[NB * NBLK];

__device__ __forceinline__ float bcef(float p, float t) {
    p = fminf(fmaxf(p, 1e-7f), 1.0f - 1e-7f);
    return -(t * logf(p) + (1.0f - t) * logf(1.0f - p));
}
__device__ __forceinline__ float sigm(float x) {
    return 1.0f / (1.0f + expf(-x));
}

// ---------------------------------------------------------------------------
// Kernel 1: per-(batch,label) preprocessing. One block per batch, 64 threads.
// ---------------------------------------------------------------------------
__global__ void prep_kernel(const float* __restrict__ labels,
                            const float* __restrict__ anchors_all,
                            const int*   __restrict__ aidx,
                            const int*   __restrict__ imgp) {
    int b = blockIdx.x;
    int k = threadIdx.x;
    __shared__ int   s_count;
    __shared__ float s_anch[18];
    __shared__ int   s_ai[NA];
    if (k == 0) s_count = 0;
    if (k < 18) s_anch[k] = anchors_all[k];
    if (k < NA) s_ai[k]   = aidx[k];
    __syncthreads();

    float img = (float)(*imgp);
    float lab[5];
    if (k < KMAX) {
        float s = 0.f;
        #pragma unroll
        for (int j = 0; j < 5; j++) { lab[j] = labels[(b*KMAX + k)*5 + j]; s += lab[j]; }
        if (s > 0.f) atomicAdd(&s_count, 1);
    }
    __syncthreads();
    if (k >= KMAX) return;

    int  nlabel  = s_count;
    bool valid_k = (k < nlabel);

    float tx = lab[1] * (float)NG, ty = lab[2] * (float)NG;
    float tw = lab[3],             th = lab[4];

    // argmax IoU against all 9 anchors (concentric boxes); first-max wins.
    int best_all = 0; float best = -1.0f;
    #pragma unroll
    for (int a = 0; a < 9; a++) {
        float aw = s_anch[2*a] / img, ah = s_anch[2*a+1] / img;
        float inter = fminf(tw, aw) * fminf(th, ah);
        float uni   = tw*th + aw*ah - inter;
        float iou   = inter / fmaxf(uni, 1e-16f);
        if (iou > best) { best = iou; best_all = a; }
    }
    bool va = false;
    #pragma unroll
    for (int j = 0; j < NA; j++) va = va || (best_all == s_ai[j]);
    int  best_n = best_all % NA;
    int  ti = (int)tx, tj = (int)ty;
    bool valid = valid_k && va && ti >= 0 && ti < NG && tj >= 0 && tj < NG;

    int   cell = -1;
    float t0 = 0.f, t1 = 0.f, t2 = 0.f, t3 = 0.f, w2 = 0.f;
    if (valid) {
        cell = (best_n * NG + tj) * NG + ti;
        t0 = tx - floorf(tx);
        t1 = ty - floorf(ty);
        float nawx = s_anch[2*s_ai[best_n]]     / img;
        float nawy = s_anch[2*s_ai[best_n] + 1] / img;
        t2 = logf(tw / nawx + 1e-16f);
        t3 = logf(th / nawy + 1e-16f);
        float sc = sqrtf(2.0f - tw * th);
        w2 = sc * sc;
    }
    // gt box for pred-IoU ignore mask is gated by valid_k (not full valid)
    float gx = 0.f, gy = 0.f, gw = 0.f, gh = 0.f;
    if (valid_k) { gx = tx / (float)NG; gy = ty / (float)NG; gw = tw; gh = th; }

    float* P = g_prep[b][k];
    P[0] = gx - gw * 0.5f;  P[1] = gy - gh * 0.5f;
    P[2] = gx + gw * 0.5f;  P[3] = gy + gh * 0.5f;
    P[4] = gw * gh;
    P[5] = t0; P[6] = t1; P[7] = t2; P[8] = t3; P[9] = w2;
    ((int*)P)[10] = cell;
    ((int*)P)[11] = (int)lab[0];
}

// ---------------------------------------------------------------------------
// Kernel 2: main loss. grid = (NBLK, NB); one thread per (a,gy,gx) cell.
// ---------------------------------------------------------------------------
__global__ void __launch_bounds__(BLK)
loss_kernel(const float* __restrict__ raw,
            const float* __restrict__ anchors_all,
            const int*   __restrict__ aidx,
            const int*   __restrict__ imgp) {
    __shared__ float4 s_box[KMAX];      // x1,y1,x2,y2
    __shared__ float2 s_meta[KMAX];     // area, cell(bits)
    __shared__ float  s_t[KMAX][5];     // t0..t3, w2
    __shared__ int    s_cls[KMAX];
    __shared__ float  s_awn[NA], s_ahn[NA];
    __shared__ double s_wsum[BLK/32];

    int b = blockIdx.y;
    int t = threadIdx.x;

    if (t < NA) {
        float img = (float)(*imgp);
        int ai = aidx[t];
        s_awn[t] = anchors_all[2*ai]     / img;
        s_ahn[t] = anchors_all[2*ai + 1] / img;
    }
    if (t < KMAX) {
        const float* P = g_prep[b][t];
        s_box[t]  = make_float4(P[0], P[1], P[2], P[3]);
        s_meta[t] = make_float2(P[4], P[10]);   // P[10] holds int bits; copy preserves bits
        s_t[t][0] = P[5]; s_t[t][1] = P[6]; s_t[t][2] = P[7];
        s_t[t][3] = P[8]; s_t[t][4] = P[9];
        s_cls[t]  = ((const int*)P)[11];
    }
    __syncthreads();

    int idx = blockIdx.x * BLK + t;
    double d = 0.0;
    if (idx < CELLS) {
        int a  = idx / (NG*NG);
        int r  = idx - a * (NG*NG);
        int gy = r / NG, gx = r - gy * NG;

        const float* base = raw + ((size_t)b * NA * NCH + a * NCH) * (NG*NG) + gy*NG + gx;
        float rx = base[0];
        float ry = base[1*NG*NG];
        float rw = base[2*NG*NG];
        float rh = base[3*NG*NG];
        float rc = base[4*NG*NG];

        float sx = sigm(rx), sy = sigm(ry), conf = sigm(rc);
        float px = (sx + (float)gx) / (float)NG;
        float py = (sy + (float)gy) / (float)NG;
        float pw = fminf(expf(rw) * s_awn[a], 1.0f);
        float ph = fminf(expf(rh) * s_ahn[a], 1.0f);

        float x1 = px - pw * 0.5f, y1 = py - ph * 0.5f;
        float x2 = px + pw * 0.5f, y2 = py + ph * 0.5f;
        float areap = pw * ph;

        bool ignore = false;
        int  winner = -1;
        unsigned m0 = 0u, m1 = 0u, m2 = 0u;

        #pragma unroll 10
        for (int k = 0; k < KMAX; k++) {
            float4 gb = s_box[k];
            float2 gm = s_meta[k];
            float iw = fminf(x2, gb.z) - fmaxf(x1, gb.x);
            float ih = fminf(y2, gb.w) - fmaxf(y1, gb.y);
            float inter = fmaxf(iw, 0.f) * fmaxf(ih, 0.f);
            // iou > 0.6  <=>  inter > 0.375*(area_p + area_g)   (union > 0 always)
            ignore = ignore || (inter > 0.375f * (areap + gm.x));
            if (__float_as_int(gm.y) == idx) {
                winner = k;                      // last writer wins
                int c = s_cls[k];
                if      (c < 32) m0 |= (1u << c);
                else if (c < 64) m1 |= (1u << (c - 32));
                else if (c < 96) m2 |= (1u << (c - 64));
            }
        }

        bool obj = (winner >= 0);
        bool pen = (!ignore) || obj;
        if (pen) d += (double)bcef(conf, obj ? 1.0f : 0.0f);

        if (obj) {
            float t0 = s_t[winner][0], t1 = s_t[winner][1];
            float t2 = s_t[winner][2], t3 = s_t[winner][3];
            float w2 = s_t[winner][4];
            d += (double)(w2 * (bcef(sx, t0) + bcef(sy, t1)));
            float dw = rw - t2, dh = rh - t3;
            d += (double)(0.5f * w2 * (dw * dw + dh * dh));
            float cls_sum = 0.f;
            #pragma unroll 8
            for (int c = 0; c < NCLS; c++) {
                float p = sigm(base[(5 + c) * NG * NG]);
                unsigned bit = (c < 32) ? (m0 >> c)
                             : (c < 64) ? (m1 >> (c - 32))
                                        : (m2 >> (c - 64));
                cls_sum += bcef(p, (float)(bit & 1u));
            }
            d += (double)cls_sum;
        }
    }

    // block reduction (double) -> deterministic partial per block
    #pragma unroll
    for (int o = 16; o > 0; o >>= 1) d += __shfl_down_sync(0xffffffffu, d, o);
    if ((t & 31) == 0) s_wsum[t >> 5] = d;
    __syncthreads();
    if (t == 0) {
        double s = 0.0;
        #pragma unroll
        for (int w = 0; w < BLK/32; w++) s += s_wsum[w];
        g_partial[blockIdx.y * gridDim.x + blockIdx.x] = s;
    }
}

// ---------------------------------------------------------------------------
// Kernel 3: deterministic final reduction.
// ---------------------------------------------------------------------------
__global__ void final_kernel(float* __restrict__ out) {
    __shared__ double sh[256];
    int t = threadIdx.x;
    double s = 0.0;
    for (int i = t; i < NB * NBLK; i += 256) s += g_partial[i];
    sh[t] = s;
    __syncthreads();
    for (int o = 128; o > 0; o >>= 1) {
        if (t < o) sh[t] += sh[t + o];
        __syncthreads();
    }
    if (t == 0) out[0] = (float)sh[0];
}

// ---------------------------------------------------------------------------
extern "C" void kernel_launch(void* const* d_in, const int* in_sizes, int n_in,
                              void* d_out, int out_size) {
    const float* raw     = (const float*)d_in[0];
    const float* labels  = (const float*)d_in[1];
    const float* anchors = (const float*)d_in[2];
    const int*   aidx    = (const int*)d_in[3];
    const int*   imgp    = (const int*)d_in[4];

    prep_kernel<<<NB, 64>>>(labels, anchors, aidx, imgp);
    dim3 grid(NBLK, NB);
    loss_kernel<<<grid, BLK>>>(raw, anchors, aidx, imgp);
    final_kernel<<<1, 256>>>((float*)d_out);
}

// round 2
// speedup vs baseline: 1.1259x; 1.1259x over previous
#include <cuda_runtime.h>
#include <stdint.h>

#define NB   16
#define KMAX 50
#define NG   76
#define NA   3
#define NCLS 80
#define NCH  85           // 5 + NCLS
#define CELLS (NA*NG*NG)  // 17328
#define BLK  256
#define NBLK ((CELLS + BLK - 1)/BLK)   // 68
#define TOTB (NB*NBLK)                 // 1088

__device__ double g_partial[TOTB];
__device__ int    g_count;             // zero-init; reset by last block each launch

__device__ __forceinline__ float bcef(float p, float t) {
    p = fminf(fmaxf(p, 1e-7f), 1.0f - 1e-7f);
    return -(t * __logf(p) + (1.0f - t) * __logf(1.0f - p));
}
__device__ __forceinline__ float sigm(float x) {
    return __fdividef(1.0f, 1.0f + __expf(-x));
}

__global__ void __launch_bounds__(BLK)
fused_kernel(const float* __restrict__ raw,
             const float* __restrict__ labels,
             const float* __restrict__ anchors_all,
             const int*   __restrict__ aidx,
             const int*   __restrict__ imgp,
             float*       __restrict__ out) {
    __shared__ float4 s_box[KMAX];      // gt corners x1,y1,x2,y2
    __shared__ float2 s_meta[KMAX];     // 0.375*area_g, cell-index bits
    __shared__ float  s_t[KMAX][5];     // t0..t3, w2
    __shared__ int    s_cls[KMAX];
    __shared__ float  s_awn[NA], s_ahn[NA];
    __shared__ int    s_cnt;
    __shared__ double s_wsum[BLK/32];
    __shared__ int    s_last;

    int b = blockIdx.y;
    int t = threadIdx.x;

    // ---------------- in-block label prep (redundant per block; tiny) -------
    if (t == 0) s_cnt = 0;
    float img = (float)(*imgp);
    if (t < NA) {
        int ai = aidx[t];
        s_awn[t] = anchors_all[2*ai]     / img;
        s_ahn[t] = anchors_all[2*ai + 1] / img;
    }
    float lab[5];
    if (t < KMAX) {
        float s = 0.f;
        #pragma unroll
        for (int j = 0; j < 5; j++) { lab[j] = labels[(b*KMAX + t)*5 + j]; s += lab[j]; }
        if (s > 0.f) atomicAdd(&s_cnt, 1);
    }
    __syncthreads();
    int nlabel = s_cnt;

    if (t < KMAX) {
        bool valid_k = (t < nlabel);
        float tx = lab[1] * (float)NG, ty = lab[2] * (float)NG;
        float tw = lab[3],             th = lab[4];

        // argmax IoU vs 9 concentric anchors (first-max wins)
        int best_all = 0; float best = -1.0f;
        #pragma unroll
        for (int a = 0; a < 9; a++) {
            float aw = anchors_all[2*a] / img, ah = anchors_all[2*a+1] / img;
            float inter = fminf(tw, aw) * fminf(th, ah);
            float uni   = tw*th + aw*ah - inter;
            float iou   = inter / fmaxf(uni, 1e-16f);
            if (iou > best) { best = iou; best_all = a; }
        }
        bool va = false;
        #pragma unroll
        for (int j = 0; j < NA; j++) va = va || (best_all == aidx[j]);
        int  best_n = best_all % NA;
        int  ti = (int)tx, tj = (int)ty;
        bool valid = valid_k && va && ti >= 0 && ti < NG && tj >= 0 && tj < NG;

        int   cell = -1;
        float t0=0.f,t1=0.f,t2=0.f,t3=0.f,w2=0.f;
        if (valid) {
            cell = (best_n * NG + tj) * NG + ti;
            t0 = tx - floorf(tx);
            t1 = ty - floorf(ty);
            t2 = __logf(tw / s_awn[best_n] + 1e-16f);
            t3 = __logf(th / s_ahn[best_n] + 1e-16f);
            w2 = 2.0f - tw * th;           // (sqrt(2-wh))^2
        }
        float gx=0.f,gy=0.f,gw=0.f,gh=0.f;
        if (valid_k) { gx = tx / (float)NG; gy = ty / (float)NG; gw = tw; gh = th; }

        s_box[t]  = make_float4(gx - gw*0.5f, gy - gh*0.5f, gx + gw*0.5f, gy + gh*0.5f);
        float2 m; m.x = 0.375f * gw * gh; m.y = __int_as_float(cell);
        s_meta[t] = m;
        s_t[t][0]=t0; s_t[t][1]=t1; s_t[t][2]=t2; s_t[t][3]=t3; s_t[t][4]=w2;
        s_cls[t]  = (int)lab[0];
    }
    __syncthreads();

    // ---------------- main per-cell loss ------------------------------------
    int idx = blockIdx.x * BLK + t;
    double d = 0.0;
    if (idx < CELLS) {
        int a  = idx / (NG*NG);
        int r  = idx - a * (NG*NG);
        int gy = r / NG, gx = r - gy * NG;

        const float* base = raw + ((size_t)b * NA * NCH + a * NCH) * (NG*NG) + gy*NG + gx;
        float rx = base[0];
        float ry = base[1*NG*NG];
        float rw = base[2*NG*NG];
        float rh = base[3*NG*NG];
        float rc = base[4*NG*NG];

        float sx = sigm(rx), sy = sigm(ry), conf = sigm(rc);
        float px = (sx + (float)gx) * (1.0f/(float)NG);
        float py = (sy + (float)gy) * (1.0f/(float)NG);
        float pw = fminf(__expf(rw) * s_awn[a], 1.0f);
        float ph = fminf(__expf(rh) * s_ahn[a], 1.0f);

        float x1 = px - pw*0.5f, y1 = py - ph*0.5f;
        float x2 = px + pw*0.5f, y2 = py + ph*0.5f;
        float ap375 = 0.375f * pw * ph;

        bool ignore = false, match = false;

        #pragma unroll 5
        for (int k = 0; k < nlabel; k++) {
            float4 gb = s_box[k];
            float2 gm = s_meta[k];
            float iw = fminf(x2, gb.z) - fmaxf(x1, gb.x);
            float ih = fminf(y2, gb.w) - fmaxf(y1, gb.y);
            float inter = fmaxf(iw, 0.f) * fmaxf(ih, 0.f);
            ignore = ignore || (inter > ap375 + gm.x);    // iou > 0.6
            match  = match  || (__float_as_int(gm.y) == idx);
        }

        if ((!ignore) || match) d += (double)bcef(conf, match ? 1.0f : 0.0f);

        if (match) {                         // rare path (~640 / 277k cells)
            int winner = 0;
            unsigned m0 = 0u, m1 = 0u, m2 = 0u;
            for (int k = 0; k < nlabel; k++) {
                if (__float_as_int(s_meta[k].y) == idx) {
                    winner = k;              // last writer wins
                    int c = s_cls[k];
                    if      (c < 32) m0 |= (1u << c);
                    else if (c < 64) m1 |= (1u << (c - 32));
                    else             m2 |= (1u << (c - 64));
                }
            }
            float t0 = s_t[winner][0], t1 = s_t[winner][1];
            float t2 = s_t[winner][2], t3 = s_t[winner][3];
            float w2 = s_t[winner][4];
            d += (double)(w2 * (bcef(sx, t0) + bcef(sy, t1)));
            float dw = rw - t2, dh = rh - t3;
            d += (double)(0.5f * w2 * (dw*dw + dh*dh));
            float cls_sum = 0.f;
            #pragma unroll 8
            for (int c = 0; c < NCLS; c++) {
                float p = sigm(base[(5 + c) * NG * NG]);
                unsigned bit = (c < 32) ? (m0 >> c)
                             : (c < 64) ? (m1 >> (c - 32))
                                        : (m2 >> (c - 64));
                cls_sum += bcef(p, (float)(bit & 1u));
            }
            d += (double)cls_sum;
        }
    }

    // ---------------- block reduction (deterministic) -----------------------
    #pragma unroll
    for (int o = 16; o > 0; o >>= 1) d += __shfl_down_sync(0xffffffffu, d, o);
    if ((t & 31) == 0) s_wsum[t >> 5] = d;
    __syncthreads();
    if (t == 0) {
        double s = 0.0;
        #pragma unroll
        for (int w = 0; w < BLK/32; w++) s += s_wsum[w];
        g_partial[blockIdx.y * gridDim.x + blockIdx.x] = s;
        __threadfence();
        int c = atomicAdd(&g_count, 1);
        s_last = (c == TOTB - 1);
    }
    __syncthreads();

    // ---------------- last block: final reduction ---------------------------
    if (s_last) {
        __shared__ double sh[BLK];
        double s = 0.0;
        for (int i = t; i < TOTB; i += BLK) s += g_partial[i];
        sh[t] = s;
        __syncthreads();
        for (int o = BLK/2; o > 0; o >>= 1) {
            if (t < o) sh[t] += sh[t + o];
            __syncthreads();
        }
        if (t == 0) { out[0] = (float)sh[0]; g_count = 0; }
    }
}

extern "C" void kernel_launch(void* const* d_in, const int* in_sizes, int n_in,
                              void* d_out, int out_size) {
    const float* raw     = (const float*)d_in[0];
    const float* labels  = (const float*)d_in[1];
    const float* anchors = (const float*)d_in[2];
    const int*   aidx    = (const int*)d_in[3];
    const int*   imgp    = (const int*)d_in[4];

    dim3 grid(NBLK, NB);
    fused_kernel<<<grid, BLK>>>(raw, labels, anchors, aidx, imgp, (float*)d_out);
}

// round 3
// speedup vs baseline: 1.8264x; 1.6222x over previous
#include <cuda_runtime.h>
#include <stdint.h>

#define NB   16
#define KMAX 50
#define NG   76
#define GG   (NG*NG)      // 5776
#define NA   3
#define NCLS 80
#define NCH  85
#define CELLS (NA*GG)     // 17328
#define CPT  4            // cells per thread
#define BLK  256
#define CPB  (BLK*CPT)    // 1024 cells per block
#define GROUPS (CELLS/CPT)            // 4332
#define NBLK ((GROUPS + BLK - 1)/BLK) // 17
#define TOTB (NB*NBLK)                // 272

__device__ double g_partial[TOTB];
__device__ int    g_count;

__device__ __forceinline__ float bcef(float p, float t) {
    p = fminf(fmaxf(p, 1e-7f), 1.0f - 1e-7f);
    return -(t * __logf(p) + (1.0f - t) * __logf(1.0f - p));
}
__device__ __forceinline__ float sigm(float x) {
    return __fdividef(1.0f, 1.0f + __expf(-x));
}

__global__ void __launch_bounds__(BLK)
fused_kernel(const float* __restrict__ raw,
             const float* __restrict__ labels,
             const float* __restrict__ anchors_all,
             const int*   __restrict__ aidx,
             const int*   __restrict__ imgp,
             float*       __restrict__ out) {
    __shared__ float4   s_box[KMAX];     // gt corners x1,y1,x2,y2
    __shared__ float    s_thr[KMAX];     // 0.375*area_g
    __shared__ int      s_cell[KMAX];    // winning cell index (batch-local), -1
    __shared__ float    s_t[KMAX][5];    // t0..t3, w2
    __shared__ int      s_cls[KMAX];
    __shared__ float    s_awn[NA], s_ahn[NA];
    __shared__ unsigned s_bits[CPB/32];  // per-block obj bitmap (32 words)
    __shared__ int      s_cnt;
    __shared__ double   s_wsum[BLK/32];
    __shared__ int      s_last;

    const int b = blockIdx.y;
    const int t = threadIdx.x;

    // ---------------- prep phase 1 ------------------------------------------
    if (t == 0) s_cnt = 0;
    if (t < CPB/32) s_bits[t] = 0u;
    float img = (float)(*imgp);
    if (t < NA) {
        int ai = aidx[t];
        s_awn[t] = anchors_all[2*ai]     / img;
        s_ahn[t] = anchors_all[2*ai + 1] / img;
    }
    float lab[5];
    if (t < KMAX) {
        float s = 0.f;
        #pragma unroll
        for (int j = 0; j < 5; j++) { lab[j] = labels[(b*KMAX + t)*5 + j]; s += lab[j]; }
        if (s > 0.f) atomicAdd(&s_cnt, 1);
    }
    __syncthreads();
    const int nlabel = s_cnt;

    // ---------------- prep phase 2 ------------------------------------------
    if (t < KMAX) {
        bool valid_k = (t < nlabel);
        float tx = lab[1] * (float)NG, ty = lab[2] * (float)NG;
        float tw = lab[3],             th = lab[4];

        int best_all = 0; float best = -1.0f;
        #pragma unroll
        for (int a = 0; a < 9; a++) {
            float aw = anchors_all[2*a] / img, ah = anchors_all[2*a+1] / img;
            float inter = fminf(tw, aw) * fminf(th, ah);
            float uni   = tw*th + aw*ah - inter;
            float iou   = inter / fmaxf(uni, 1e-16f);
            if (iou > best) { best = iou; best_all = a; }
        }
        bool va = false;
        #pragma unroll
        for (int j = 0; j < NA; j++) va = va || (best_all == aidx[j]);
        int  best_n = best_all % NA;
        int  ti = (int)tx, tj = (int)ty;
        bool valid = valid_k && va && ti >= 0 && ti < NG && tj >= 0 && tj < NG;

        int   cell = -1;
        float t0=0.f,t1=0.f,t2=0.f,t3=0.f,w2=0.f;
        if (valid) {
            cell = (best_n * NG + tj) * NG + ti;
            t0 = tx - floorf(tx);
            t1 = ty - floorf(ty);
            t2 = __logf(tw / s_awn[best_n] + 1e-16f);
            t3 = __logf(th / s_ahn[best_n] + 1e-16f);
            w2 = 2.0f - tw * th;
            int local = cell - blockIdx.x * CPB;
            if (local >= 0 && local < CPB)
                atomicOr(&s_bits[local >> 5], 1u << (local & 31));
        }
        float gx=0.f,gy=0.f,gw=0.f,gh=0.f;
        if (valid_k) { gx = tx / (float)NG; gy = ty / (float)NG; gw = tw; gh = th; }

        s_box[t]  = make_float4(gx - gw*0.5f, gy - gh*0.5f, gx + gw*0.5f, gy + gh*0.5f);
        s_thr[t]  = 0.375f * gw * gh;
        s_cell[t] = cell;
        s_t[t][0]=t0; s_t[t][1]=t1; s_t[t][2]=t2; s_t[t][3]=t3; s_t[t][4]=w2;
        s_cls[t]  = (int)lab[0];
    }
    __syncthreads();

    // ---------------- main: 4 adjacent cells per thread ---------------------
    const int gidx = blockIdx.x * BLK + t;
    double d = 0.0;
    if (gidx < GROUPS) {
        const int cell0 = gidx * CPT;
        const int a  = cell0 / GG;
        const int r  = cell0 - a * GG;
        const int gy = r / NG, gx0 = r - gy * NG;   // gx0 % 4 == 0

        const float* base = raw + ((size_t)(b*NA + a) * NCH) * GG + gy*NG + gx0;
        float4 vx = *(const float4*)(base + 0*GG);
        float4 vy = *(const float4*)(base + 1*GG);
        float4 vw = *(const float4*)(base + 2*GG);
        float4 vh = *(const float4*)(base + 3*GG);
        float4 vc = *(const float4*)(base + 4*GG);

        float RX[CPT] = {vx.x, vx.y, vx.z, vx.w};
        float RY[CPT] = {vy.x, vy.y, vy.z, vy.w};
        float RW[CPT] = {vw.x, vw.y, vw.z, vw.w};
        float RH[CPT] = {vh.x, vh.y, vh.z, vh.w};
        float RC[CPT] = {vc.x, vc.y, vc.z, vc.w};

        float SX[CPT], SY[CPT], CF[CPT];
        float X1[CPT], Y1[CPT], X2[CPT], Y2[CPT], AP[CPT], MD[CPT];
        const float awn = s_awn[a], ahn = s_ahn[a];
        const float inv = 1.0f / (float)NG;
        #pragma unroll
        for (int c = 0; c < CPT; c++) {
            SX[c] = sigm(RX[c]); SY[c] = sigm(RY[c]); CF[c] = sigm(RC[c]);
            float px = (SX[c] + (float)(gx0 + c)) * inv;
            float py = (SY[c] + (float)gy) * inv;
            float pw = fminf(__expf(RW[c]) * awn, 1.0f);
            float ph = fminf(__expf(RH[c]) * ahn, 1.0f);
            X1[c] = px - pw*0.5f; Y1[c] = py - ph*0.5f;
            X2[c] = px + pw*0.5f; Y2[c] = py + ph*0.5f;
            AP[c] = 0.375f * pw * ph;
            MD[c] = -1e30f;
        }

        #pragma unroll 2
        for (int k = 0; k < nlabel; k++) {
            const float4 gb = s_box[k];
            const float  th = s_thr[k];
            #pragma unroll
            for (int c = 0; c < CPT; c++) {
                float iw = fminf(X2[c], gb.z) - fmaxf(X1[c], gb.x);
                float ih = fminf(Y2[c], gb.w) - fmaxf(Y1[c], gb.y);
                float inter = fmaxf(iw, 0.f) * fmaxf(ih, 0.f);
                MD[c] = fmaxf(MD[c], inter - th);
            }
        }

        #pragma unroll
        for (int c = 0; c < CPT; c++) {
            bool ign = MD[c] > AP[c];
            int  local = t * CPT + c;
            bool obj = (s_bits[local >> 5] >> (local & 31)) & 1u;
            if ((!ign) || obj) d += (double)bcef(CF[c], obj ? 1.0f : 0.0f);

            if (obj) {                            // rare (~640 cells total)
                const int cellg = cell0 + c;
                int winner = 0;
                unsigned m0 = 0u, m1 = 0u, m2 = 0u;
                for (int k = 0; k < nlabel; k++) {
                    if (s_cell[k] == cellg) {
                        winner = k;               // last writer wins
                        int cc = s_cls[k];
                        if      (cc < 32) m0 |= (1u << cc);
                        else if (cc < 64) m1 |= (1u << (cc - 32));
                        else              m2 |= (1u << (cc - 64));
                    }
                }
                float t0 = s_t[winner][0], t1 = s_t[winner][1];
                float t2 = s_t[winner][2], t3 = s_t[winner][3];
                float w2 = s_t[winner][4];
                d += (double)(w2 * (bcef(SX[c], t0) + bcef(SY[c], t1)));
                float dw = RW[c] - t2, dh = RH[c] - t3;
                d += (double)(0.5f * w2 * (dw*dw + dh*dh));
                float cls_sum = 0.f;
                #pragma unroll 8
                for (int cc = 0; cc < NCLS; cc++) {
                    float p = sigm(base[(5 + cc) * GG + c]);
                    unsigned bit = (cc < 32) ? (m0 >> cc)
                                 : (cc < 64) ? (m1 >> (cc - 32))
                                             : (m2 >> (cc - 64));
                    cls_sum += bcef(p, (float)(bit & 1u));
                }
                d += (double)cls_sum;
            }
        }
    }

    // ---------------- block reduction (deterministic) -----------------------
    #pragma unroll
    for (int o = 16; o > 0; o >>= 1) d += __shfl_down_sync(0xffffffffu, d, o);
    if ((t & 31) == 0) s_wsum[t >> 5] = d;
    __syncthreads();
    if (t == 0) {
        double s = 0.0;
        #pragma unroll
        for (int w = 0; w < BLK/32; w++) s += s_wsum[w];
        g_partial[blockIdx.y * gridDim.x + blockIdx.x] = s;
        __threadfence();
        int c = atomicAdd(&g_count, 1);
        s_last = (c == TOTB - 1);
    }
    __syncthreads();

    // ---------------- last block: final reduction ---------------------------
    if (s_last) {
        __shared__ double sh[BLK];
        double s = 0.0;
        for (int i = t; i < TOTB; i += BLK) s += g_partial[i];
        sh[t] = s;
        __syncthreads();
        for (int o = BLK/2; o > 0; o >>= 1) {
            if (t < o) sh[t] += sh[t + o];
            __syncthreads();
        }
        if (t == 0) { out[0] = (float)sh[0]; g_count = 0; }
    }
}

extern "C" void kernel_launch(void* const* d_in, const int* in_sizes, int n_in,
                              void* d_out, int out_size) {
    const float* raw     = (const float*)d_in[0];
    const float* labels  = (const float*)d_in[1];
    const float* anchors = (const float*)d_in[2];
    const int*   aidx    = (const int*)d_in[3];
    const int*   imgp    = (const int*)d_in[4];

    dim3 grid(NBLK, NB);
    fused_kernel<<<grid, BLK>>>(raw, labels, anchors, aidx, imgp, (float*)d_out);
}

// round 4
// speedup vs baseline: 1.8289x; 1.0014x over previous
#include <cuda_runtime.h>
#include <stdint.h>

#define NB   16
#define KMAX 50
#define NG   76
#define GG   (NG*NG)      // 5776
#define NA   3
#define NCLS 80
#define NCH  85
#define CELLS (NA*GG)     // 17328
#define CPT  2            // cells per thread
#define BLK  256
#define CPB  (BLK*CPT)    // 512 cells per block
#define GROUPS (CELLS/CPT)            // 8664
#define NBLK ((GROUPS + BLK - 1)/BLK) // 34
#define TOTB (NB*NBLK)                // 544

__device__ double g_partial[TOTB];
__device__ int    g_count;

__device__ __forceinline__ float bcef(float p, float t) {
    p = fminf(fmaxf(p, 1e-7f), 1.0f - 1e-7f);
    return -(t * __logf(p) + (1.0f - t) * __logf(1.0f - p));
}
__device__ __forceinline__ float sigm(float x) {
    return __fdividef(1.0f, 1.0f + __expf(-x));
}

__global__ void __launch_bounds__(BLK)
fused_kernel(const float* __restrict__ raw,
             const float* __restrict__ labels,
             const float* __restrict__ anchors_all,
             const int*   __restrict__ aidx,
             const int*   __restrict__ imgp,
             float*       __restrict__ out) {
    __shared__ float4   s_box[KMAX];     // gt corners x1,y1,x2,y2
    __shared__ float    s_thr[KMAX];     // 0.375*area_g
    __shared__ int      s_cell[KMAX];    // winning cell index (batch-local), -1
    __shared__ float    s_t[KMAX][5];    // t0..t3, w2
    __shared__ int      s_cls[KMAX];
    __shared__ float    s_awn[NA], s_ahn[NA];
    __shared__ unsigned s_bits[CPB/32];  // per-block obj bitmap (16 words)
    __shared__ int      s_cnt;
    __shared__ double   s_wsum[BLK/32];
    __shared__ int      s_last;

    const int b = blockIdx.y;
    const int t = threadIdx.x;

    // ---------------- prep phase 1 ------------------------------------------
    if (t == 0) s_cnt = 0;
    if (t < CPB/32) s_bits[t] = 0u;
    float img = (float)(*imgp);
    if (t < NA) {
        int ai = aidx[t];
        s_awn[t] = anchors_all[2*ai]     / img;
        s_ahn[t] = anchors_all[2*ai + 1] / img;
    }
    float lab[5];
    if (t < KMAX) {
        float s = 0.f;
        #pragma unroll
        for (int j = 0; j < 5; j++) { lab[j] = labels[(b*KMAX + t)*5 + j]; s += lab[j]; }
        if (s > 0.f) atomicAdd(&s_cnt, 1);
    }
    __syncthreads();
    const int nlabel = s_cnt;

    // ---------------- prep phase 2 ------------------------------------------
    if (t < KMAX) {
        bool valid_k = (t < nlabel);
        float tx = lab[1] * (float)NG, ty = lab[2] * (float)NG;
        float tw = lab[3],             th = lab[4];

        int best_all = 0; float best = -1.0f;
        #pragma unroll
        for (int a = 0; a < 9; a++) {
            float aw = anchors_all[2*a] / img, ah = anchors_all[2*a+1] / img;
            float inter = fminf(tw, aw) * fminf(th, ah);
            float uni   = tw*th + aw*ah - inter;
            float iou   = inter / fmaxf(uni, 1e-16f);
            if (iou > best) { best = iou; best_all = a; }
        }
        bool va = false;
        #pragma unroll
        for (int j = 0; j < NA; j++) va = va || (best_all == aidx[j]);
        int  best_n = best_all % NA;
        int  ti = (int)tx, tj = (int)ty;
        bool valid = valid_k && va && ti >= 0 && ti < NG && tj >= 0 && tj < NG;

        int   cell = -1;
        float t0=0.f,t1=0.f,t2=0.f,t3=0.f,w2=0.f;
        if (valid) {
            cell = (best_n * NG + tj) * NG + ti;
            t0 = tx - floorf(tx);
            t1 = ty - floorf(ty);
            t2 = __logf(tw / s_awn[best_n] + 1e-16f);
            t3 = __logf(th / s_ahn[best_n] + 1e-16f);
            w2 = 2.0f - tw * th;
            int local = cell - blockIdx.x * CPB;
            if (local >= 0 && local < CPB)
                atomicOr(&s_bits[local >> 5], 1u << (local & 31));
        }
        float gx=0.f,gy=0.f,gw=0.f,gh=0.f;
        if (valid_k) { gx = tx / (float)NG; gy = ty / (float)NG; gw = tw; gh = th; }

        s_box[t]  = make_float4(gx - gw*0.5f, gy - gh*0.5f, gx + gw*0.5f, gy + gh*0.5f);
        s_thr[t]  = 0.375f * gw * gh;
        s_cell[t] = cell;
        s_t[t][0]=t0; s_t[t][1]=t1; s_t[t][2]=t2; s_t[t][3]=t3; s_t[t][4]=w2;
        s_cls[t]  = (int)lab[0];
    }
    __syncthreads();

    // ---------------- main: 2 adjacent cells per thread ---------------------
    const int gidx = blockIdx.x * BLK + t;
    double d = 0.0;
    if (gidx < GROUPS) {
        const int cell0 = gidx * CPT;
        const int a  = cell0 / GG;
        const int r  = cell0 - a * GG;
        const int gy = r / NG, gx0 = r - gy * NG;   // gx0 % 2 == 0

        const float* base = raw + ((size_t)(b*NA + a) * NCH) * GG + gy*NG + gx0;
        float2 vx = *(const float2*)(base + 0*GG);
        float2 vy = *(const float2*)(base + 1*GG);
        float2 vw = *(const float2*)(base + 2*GG);
        float2 vh = *(const float2*)(base + 3*GG);
        float2 vc = *(const float2*)(base + 4*GG);

        float RX[CPT] = {vx.x, vx.y};
        float RY[CPT] = {vy.x, vy.y};
        float RW[CPT] = {vw.x, vw.y};
        float RH[CPT] = {vh.x, vh.y};
        float RC[CPT] = {vc.x, vc.y};

        float SX[CPT], SY[CPT], CF[CPT];
        float X1[CPT], Y1[CPT], X2[CPT], Y2[CPT], AP[CPT], MD[CPT];
        const float awn = s_awn[a], ahn = s_ahn[a];
        const float inv = 1.0f / (float)NG;
        #pragma unroll
        for (int c = 0; c < CPT; c++) {
            SX[c] = sigm(RX[c]); SY[c] = sigm(RY[c]); CF[c] = sigm(RC[c]);
            float px = (SX[c] + (float)(gx0 + c)) * inv;
            float py = (SY[c] + (float)gy) * inv;
            float pw = fminf(__expf(RW[c]) * awn, 1.0f);
            float ph = fminf(__expf(RH[c]) * ahn, 1.0f);
            X1[c] = px - pw*0.5f; Y1[c] = py - ph*0.5f;
            X2[c] = px + pw*0.5f; Y2[c] = py + ph*0.5f;
            AP[c] = 0.375f * pw * ph;
            MD[c] = -1e30f;
        }

        #pragma unroll 4
        for (int k = 0; k < nlabel; k++) {
            const float4 gb = s_box[k];
            const float  th = s_thr[k];
            #pragma unroll
            for (int c = 0; c < CPT; c++) {
                float iw = fminf(X2[c], gb.z) - fmaxf(X1[c], gb.x);
                float ih = fminf(Y2[c], gb.w) - fmaxf(Y1[c], gb.y);
                float inter = fmaxf(iw, 0.f) * fmaxf(ih, 0.f);
                MD[c] = fmaxf(MD[c], inter - th);
            }
        }

        #pragma unroll
        for (int c = 0; c < CPT; c++) {
            bool ign = MD[c] > AP[c];
            int  local = t * CPT + c;
            bool obj = (s_bits[local >> 5] >> (local & 31)) & 1u;
            if ((!ign) || obj) d += (double)bcef(CF[c], obj ? 1.0f : 0.0f);

            if (obj) {                            // rare (~640 cells total)
                const int cellg = cell0 + c;
                int winner = 0;
                unsigned m0 = 0u, m1 = 0u, m2 = 0u;
                for (int k = 0; k < nlabel; k++) {
                    if (s_cell[k] == cellg) {
                        winner = k;               // last writer wins
                        int cc = s_cls[k];
                        if      (cc < 32) m0 |= (1u << cc);
                        else if (cc < 64) m1 |= (1u << (cc - 32));
                        else              m2 |= (1u << (cc - 64));
                    }
                }
                float t0 = s_t[winner][0], t1 = s_t[winner][1];
                float t2 = s_t[winner][2], t3 = s_t[winner][3];
                float w2 = s_t[winner][4];
                d += (double)(w2 * (bcef(SX[c], t0) + bcef(SY[c], t1)));
                float dw = RW[c] - t2, dh = RH[c] - t3;
                d += (double)(0.5f * w2 * (dw*dw + dh*dh));
                float cls_sum = 0.f;
                #pragma unroll 8
                for (int cc = 0; cc < NCLS; cc++) {
                    float p = sigm(base[(5 + cc) * GG + c]);
                    unsigned bit = (cc < 32) ? (m0 >> cc)
                                 : (cc < 64) ? (m1 >> (cc - 32))
                                             : (m2 >> (cc - 64));
                    cls_sum += bcef(p, (float)(bit & 1u));
                }
                d += (double)cls_sum;
            }
        }
    }

    // ---------------- block reduction (deterministic) -----------------------
    #pragma unroll
    for (int o = 16; o > 0; o >>= 1) d += __shfl_down_sync(0xffffffffu, d, o);
    if ((t & 31) == 0) s_wsum[t >> 5] = d;
    __syncthreads();
    if (t == 0) {
        double s = 0.0;
        #pragma unroll
        for (int w = 0; w < BLK/32; w++) s += s_wsum[w];
        g_partial[blockIdx.y * gridDim.x + blockIdx.x] = s;
        __threadfence();
        int c = atomicAdd(&g_count, 1);
        s_last = (c == TOTB - 1);
    }
    __syncthreads();

    // ---------------- last block: final reduction ---------------------------
    if (s_last) {
        __shared__ double sh[BLK];
        double s = 0.0;
        for (int i = t; i < TOTB; i += BLK) s += g_partial[i];
        sh[t] = s;
        __syncthreads();
        for (int o = BLK/2; o > 0; o >>= 1) {
            if (t < o) sh[t] += sh[t + o];
            __syncthreads();
        }
        if (t == 0) { out[0] = (float)sh[0]; g_count = 0; }
    }
}

extern "C" void kernel_launch(void* const* d_in, const int* in_sizes, int n_in,
                              void* d_out, int out_size) {
    const float* raw     = (const float*)d_in[0];
    const float* labels  = (const float*)d_in[1];
    const float* anchors = (const float*)d_in[2];
    const int*   aidx    = (const int*)d_in[3];
    const int*   imgp    = (const int*)d_in[4];

    dim3 grid(NBLK, NB);
    fused_kernel<<<grid, BLK>>>(raw, labels, anchors, aidx, imgp, (float*)d_out);
}